// round 9
// baseline (speedup 1.0000x reference)
#include <cuda_runtime.h>

#define EPSB 1e-5f
#define NB 16

// ---------------- device-global scratch (no allocation allowed) ----------------
// activation ping-pong buffers: packed SIGNED int8 codes, already requantized to
// the CONSUMER block's input scale (producer-side LUT). NHWC.
__device__ __align__(128) unsigned char g_actA[NB * 160 * 320 * 16]; // 13.1 MB
__device__ __align__(128) unsigned char g_actB[NB * 80 * 160 * 32];  //  6.6 MB

// packed int8x4 quantized weights, layout per weight: [tap][cin4][cout]
__device__ int   g_wq[52560];
__device__ float g_sw[9];        // per-tensor weight scales
__device__ float g_A[512];       // per-block (8) x per-channel epilogue scale
__device__ float g_B[512];       // per-block bias
__device__ float g_head_sc;      // s_w9 * scales[9]

// ---------------- prep kernels ----------------
struct MaxArgs { const float* p[9]; int n[9]; };

__global__ void k_maxabs(MaxArgs a) {
    __shared__ float red[8];
    const int b = blockIdx.x;
    const float* __restrict__ w = a.p[b];
    const int n = a.n[b];
    float m = 0.f;
    for (int i = threadIdx.x; i < n; i += blockDim.x) m = fmaxf(m, fabsf(w[i]));
    for (int s = 16; s; s >>= 1) m = fmaxf(m, __shfl_xor_sync(0xffffffffu, m, s));
    if ((threadIdx.x & 31) == 0) red[threadIdx.x >> 5] = m;
    __syncthreads();
    if (threadIdx.x < 32) {
        float v = (threadIdx.x < 8) ? red[threadIdx.x] : 0.f;
        for (int s = 4; s; s >>= 1) v = fmaxf(v, __shfl_xor_sync(0xffffffffu, v, s));
        if (threadIdx.x == 0) g_sw[b] = v / 7.0f;
    }
}

struct PackArgs { const float* w[9]; };

__global__ void k_pack(PackArgs a) {
    const int off[10]  = {0, 144, 1296, 5904, 15120, 24336, 33552, 42768, 51984, 52560};
    const int cinR[9]  = {3, 16, 32, 64, 64, 64, 64, 64, 64};
    const int cin4[9]  = {1, 4, 8, 16, 16, 16, 16, 16, 16};
    const int coutA[9] = {16, 32, 64, 64, 64, 64, 64, 64, 36};
    const int kk[9]    = {3, 3, 3, 3, 3, 3, 3, 3, 1};

    int idx = blockIdx.x * blockDim.x + threadIdx.x;
    if (idx >= 52560) return;
    int wi = 0;
    while (wi < 8 && idx >= off[wi + 1]) wi++;
    const int local = idx - off[wi];
    const int C4 = cin4[wi], CO = coutA[wi], K = kk[wi], CR = cinR[wi];
    const int tap = local / (C4 * CO);
    const int rest = local % (C4 * CO);
    const int c4 = rest / CO, o = rest % CO;
    const int ky = tap / K, kx = tap % K;
    const float s = g_sw[wi];
    const float* __restrict__ w = a.w[wi];
    unsigned packed = 0;
#pragma unroll
    for (int j = 0; j < 4; j++) {
        const int ci = c4 * 4 + j;
        int q = 0;
        if (ci < CR) {
            float v = w[((o * CR + ci) * K + ky) * K + kx];
            q = __float2int_rn(__fdiv_rn(v, s));
            q = min(7, max(-7, q));
        }
        packed |= (unsigned)(q & 255) << (j * 8);
    }
    g_wq[idx] = (int)packed;
}

struct BnArgs { const float* bn[8]; const float* scales; };

__global__ void k_params(BnArgs a) {
    const int couts[8] = {16, 32, 64, 64, 64, 64, 64, 64};
    for (int idx = threadIdx.x; idx < 8 * 64; idx += blockDim.x) {
        const int blk = idx >> 6, c = idx & 63;
        const int C = couts[blk];
        if (c >= C) continue;
        const float* __restrict__ bn = a.bn[blk];
        const float g = bn[c], b = bn[C + c], m = bn[2 * C + c], v = bn[3 * C + c];
        const float inv = __fdiv_rn(g, sqrtf(v + EPSB));
        const float s_in = a.scales[1 + blk];
        const float s_relu = a.scales[10 + blk];
        const float sw = g_sw[blk];
        g_A[idx] = __fdiv_rn(sw * s_in * inv, s_relu);
        g_B[idx] = __fdiv_rn(b - m * inv, s_relu);
    }
    if (threadIdx.x == 0) g_head_sc = g_sw[8] * a.scales[9];
}

// ---------------- generic fused conv block ----------------
// NH = channel-split factor: CTA has 256*NH threads; warps [0,8) compute couts
// [0,COUT/NH), warps [8,16) the rest, over the SAME 16x16 pixel tile.
// Input: packed signed int8 codes already in THIS block's input scale.
// 3x3 SAME conv via dp4a, BN epilogue, clamp to q15, producer-side LUT to next
// block's input code. Pooling: int-domain shfl max over lane quads, lane-split
// requant (each lane does CO/4 channels).
template <int CIN4, int COUT, bool POOL, int NH>
__global__ __launch_bounds__(256 * NH) void
k_conv(int inSel, int outSel, int woff, const float* __restrict__ scales,
       int sRelu, int sNext, int blk, int H, int W)
{
    constexpr int NT   = 256 * NH;
    constexpr int CO   = COUT / NH;         // couts per thread
    constexpr int CIN  = CIN4 * 4;
    constexpr int XS   = CIN4 + 1;          // +1 word pad: bank-conflict mitigation
    constexpr int NW   = 9 * CIN4 * COUT;
    constexpr int NC16 = CIN4 / 4;          // 16B chunks per pixel

    extern __shared__ int smem[];
    int*   sw_  = smem;                     // weights [tap][c4][o]
    int*   sx   = smem + NW;                // input tile 18x18, packed int8x4
    float* sA   = (float*)(sx + 324 * XS);
    float* sB   = sA + COUT;
    int*   slut = (int*)(sB + COUT);        // q15 -> next-input code (byte)

    const unsigned char* __restrict__ in  = inSel  ? g_actB : g_actA;
    unsigned char*       __restrict__ out = outSel ? g_actB : g_actA;

    const int tid = threadIdx.x;
    if (tid < 16) {
        const float sp = scales[sRelu], sc = scales[sNext];
        int v = __float2int_rn(__fdiv_rn((float)tid * sp, sc));
        slut[tid] = min(7, max(-8, v)) & 255;
    }
    if (tid < COUT) { sA[tid] = g_A[blk * 64 + tid]; sB[tid] = g_B[blk * 64 + tid]; }
    {   // vectorized weight fill (woff and NW are 16B-aligned)
        const int4* __restrict__ wq4 = reinterpret_cast<const int4*>(g_wq + woff);
        int4* sw4 = reinterpret_cast<int4*>(sw_);
        for (int i = tid; i < NW / 4; i += NT) sw4[i] = wq4[i];
    }

    const int b  = blockIdx.z;
    const int x0 = blockIdx.x * 16, y0 = blockIdx.y * 16;

    // cooperative halo tile copy (raw — codes are pre-requantized by producer)
    for (int i = tid; i < 324 * NC16; i += NT) {
        const int pix = i / NC16, c16 = i % NC16;
        const int ty = pix / 18, tx = pix % 18;
        const int iy = y0 + ty - 1, ix = x0 + tx - 1;
        uint4 v = make_uint4(0, 0, 0, 0);
        if (iy >= 0 && iy < H && ix >= 0 && ix < W)
            v = *reinterpret_cast<const uint4*>(
                in + ((size_t)(b * H + iy) * W + ix) * CIN + c16 * 16);
        int* d = sx + pix * XS + c16 * 4;
        d[0] = (int)v.x; d[1] = (int)v.y; d[2] = (int)v.z; d[3] = (int)v.w;
    }
    __syncthreads();

    const int lane = tid & 31, warp = tid >> 5;
    const int chbase = (warp >> 3) * CO;              // 0 for NH=1
    const int quad = ((warp & 7) << 3) + (lane >> 2); // pixel quad (shared by halves)
    const int px = ((quad & 7) << 1) + (lane & 1);
    const int py = ((quad >> 3) << 1) + ((lane >> 1) & 1);

    int acc[CO];
#pragma unroll
    for (int o = 0; o < CO; o++) acc[o] = 0;

#pragma unroll
    for (int ky = 0; ky < 3; ky++)
#pragma unroll
    for (int kx = 0; kx < 3; kx++) {
        const int* __restrict__ xr = sx + ((py + ky) * 18 + (px + kx)) * XS;
        const int* __restrict__ wp = sw_ + (ky * 3 + kx) * CIN4 * COUT + chbase;
        for (int c4 = 0; c4 < CIN4; c4++) {
            const int xw = xr[c4];
            const int* __restrict__ w = wp + c4 * COUT;
#pragma unroll
            for (int o = 0; o < CO; o += 4) {      // LDS.128 broadcast weight loads
                const int4 w4 = *reinterpret_cast<const int4*>(w + o);
                acc[o + 0] = __dp4a(xw, w4.x, acc[o + 0]);
                acc[o + 1] = __dp4a(xw, w4.y, acc[o + 1]);
                acc[o + 2] = __dp4a(xw, w4.z, acc[o + 2]);
                acc[o + 3] = __dp4a(xw, w4.w, acc[o + 3]);
            }
        }
    }

    const int gx = x0 + px, gy = y0 + py;

    if (POOL) {
        // pool in integer domain (A>0 => affine+rint+clip monotone)
#pragma unroll
        for (int o = 0; o < CO; o++) {
            int a = acc[o];
            a = max(a, __shfl_xor_sync(0xffffffffu, a, 1));
            a = max(a, __shfl_xor_sync(0xffffffffu, a, 2));
            acc[o] = a;
        }
        constexpr int Cq = CO / 4;             // channels per lane (8 for CO=32)
        const int q4 = lane & 3;
        const int base = chbase + q4 * Cq;
        unsigned pk[Cq / 4];
#pragma unroll
        for (int j = 0; j < Cq / 4; j++) pk[j] = 0;
#pragma unroll
        for (int j = 0; j < Cq; j++) {
            const int o = q4 * Cq + j;           // index within this thread's CO
            const int oc = base + j;             // absolute cout
            const float y = fmaf((float)acc[o], sA[oc], sB[oc]);
            int q = __float2int_rn(y);
            q = min(15, max(0, q));
            pk[j >> 2] |= (unsigned)slut[q] << ((j & 3) * 8);
        }
        if (gy < H && gx < W) {
            const int Ho = H >> 1, Wo = W >> 1;
            unsigned char* dst = out
                + ((size_t)(b * Ho + (gy >> 1)) * Wo + (gx >> 1)) * COUT + base;
            if (Cq >= 16)
                *reinterpret_cast<uint4*>(dst) =
                    make_uint4(pk[0], pk[1 % (Cq/4)], pk[2 % (Cq/4)], pk[3 % (Cq/4)]);
            else
                *reinterpret_cast<uint2*>(dst) = make_uint2(pk[0], pk[1 % (Cq/4)]);
        }
    } else {
        unsigned pk[CO / 4];
#pragma unroll
        for (int o = 0; o < CO; o++) {
            const float y = fmaf((float)acc[o], sA[chbase + o], sB[chbase + o]);
            int q = __float2int_rn(y);
            q = min(15, max(0, q));
            if ((o & 3) == 0) pk[o >> 2] = (unsigned)slut[q];
            else              pk[o >> 2] |= (unsigned)slut[q] << ((o & 3) * 8);
        }
        if (gy < H && gx < W) {
            unsigned char* dst =
                out + ((size_t)(b * H + gy) * W + gx) * COUT + chbase;
#pragma unroll
            for (int j = 0; j < CO / 16; j++)
                *reinterpret_cast<uint4*>(dst + 16 * j) =
                    make_uint4(pk[4 * j], pk[4 * j + 1], pk[4 * j + 2], pk[4 * j + 3]);
        }
    }
}

// ---------------- block 0: float NCHW input, pair-per-thread, 512 threads ----------------
// Thread owns a 1x2 horizontal pixel pair (acc[2][16]); vertical pool partner is
// lane^1 (lane = y). Quant chain: q0 = clamp(rint(x*rcp(s0))) -> lut01 -> s1
// codes -> conv -> int-domain pool -> BN requant -> lut2 -> s2 codes.
__global__ __launch_bounds__(512) void
k_conv_first(const float* __restrict__ xin, const float* __restrict__ scales)
{
    const int H = 320, W = 640;
    __shared__ int   sw_[144];
    __shared__ int   sx[34 * 35];            // 34 rows, stride 35 (odd => conflict-free)
    __shared__ float sA[16], sB[16];
    __shared__ int   lut01[16];              // (q0+8) -> s1 code byte
    __shared__ int   lut2[16];               // q15 -> s2 code byte

    const int tid = threadIdx.x;
    if (tid < 16) {
        const float s0 = scales[0], s1 = scales[1];
        int v = __float2int_rn(__fdiv_rn((float)(tid - 8) * s0, s1));
        lut01[tid] = min(7, max(-8, v)) & 255;
        int u = __float2int_rn(__fdiv_rn((float)tid * scales[10], scales[2]));
        lut2[tid] = min(7, max(-8, u)) & 255;
        sA[tid] = g_A[tid]; sB[tid] = g_B[tid];
    }
    for (int i = tid; i < 144; i += 512) sw_[i] = g_wq[i];
    __syncthreads();   // halo loop reads lut01

    const float r0 = __frcp_rn(__ldg(&scales[0]));
    const int b = blockIdx.z;
    const int x0 = blockIdx.x * 32, y0 = blockIdx.y * 32;

    // halo 34x34, quantize+LUT+pack (3 channels per word)
    for (int i = tid; i < 34 * 34; i += 512) {
        const int ty = i / 34, tx = i % 34;
        const int iy = y0 + ty - 1, ix = x0 + tx - 1;
        unsigned pkd = 0;
        if (iy >= 0 && iy < H && ix >= 0 && ix < W) {
            const size_t base = (size_t)b * 3 * H * W + (size_t)iy * W + ix;
#pragma unroll
            for (int c = 0; c < 3; c++) {
                const float f = xin[base + (size_t)c * H * W];
                int q0 = __float2int_rn(f * r0);
                q0 = min(7, max(-8, q0));
                pkd |= (unsigned)lut01[q0 + 8] << (8 * c);
            }
        }
        sx[ty * 35 + tx] = (int)pkd;
    }
    __syncthreads();

    const int y  = tid & 31;                 // == lane; vertical partner = lane^1
    const int xp = tid >> 5;                 // 16 column pairs

    int win[3][4];                           // rows y..y+2, cols 2xp..2xp+3 (halo coords)
#pragma unroll
    for (int dy = 0; dy < 3; dy++)
#pragma unroll
    for (int dx = 0; dx < 4; dx++)
        win[dy][dx] = sx[(y + dy) * 35 + 2 * xp + dx];

    int acc[2][16];
#pragma unroll
    for (int p = 0; p < 2; p++)
#pragma unroll
    for (int o = 0; o < 16; o++) acc[p][o] = 0;

#pragma unroll
    for (int ky = 0; ky < 3; ky++)
#pragma unroll
    for (int kx = 0; kx < 3; kx++) {
        const int* __restrict__ w = sw_ + (ky * 3 + kx) * 16;
        int4 w4[4];
#pragma unroll
        for (int j = 0; j < 4; j++) w4[j] = *reinterpret_cast<const int4*>(w + 4 * j);
#pragma unroll
        for (int p = 0; p < 2; p++) {
            const int xw = win[ky][kx + p];
#pragma unroll
            for (int j = 0; j < 4; j++) {
                acc[p][4 * j + 0] = __dp4a(xw, w4[j].x, acc[p][4 * j + 0]);
                acc[p][4 * j + 1] = __dp4a(xw, w4[j].y, acc[p][4 * j + 1]);
                acc[p][4 * j + 2] = __dp4a(xw, w4[j].z, acc[p][4 * j + 2]);
                acc[p][4 * j + 3] = __dp4a(xw, w4[j].w, acc[p][4 * j + 3]);
            }
        }
    }

    // horizontal pool in-thread, vertical pool via shfl, then lane-parity
    // channel split: even y does ch 0-7, odd y does ch 8-15.
    const int hb = (y & 1) * 8;
    unsigned pk[2];
    pk[0] = pk[1] = 0;
#pragma unroll
    for (int o = 0; o < 16; o++) {
        int m = max(acc[0][o], acc[1][o]);
        m = max(m, __shfl_xor_sync(0xffffffffu, m, 1));
        if (o >= hb && o < hb + 8) {
            const float yv = fmaf((float)m, sA[o], sB[o]);
            int q = __float2int_rn(yv);
            q = min(15, max(0, q));
            const int j = o - hb;
            pk[j >> 2] |= (unsigned)lut2[q] << ((j & 3) * 8);
        }
    }

    const int gx = (x0 >> 1) + xp, gy = (y0 + y) >> 1;   // pooled coords, exact cover
    *reinterpret_cast<uint2*>(
        g_actA + ((size_t)(b * 160 + gy) * 320 + gx) * 16 + hb)
        = make_uint2(pk[0], pk[1]);
}

// ---------------- head: 1x1 conv (64->36) + bias, fp32 NCHW out ----------------
// Input codes are already in scales[9] units (block7 producer LUT) — no requant.
__global__ __launch_bounds__(256) void
k_head(float* __restrict__ outp, const float* __restrict__ b9)
{
    __shared__ int   sw_[576];
    __shared__ float s_sc;
    const int tid = threadIdx.x;
    if (tid == 0) s_sc = g_head_sc;
    for (int i = tid; i < 576; i += 256) sw_[i] = g_wq[51984 + i];
    __syncthreads();

    const int p = blockIdx.x * 256 + tid;      // 0..12799 = b*800 + y*40 + x
    if (p >= 12800) return;
    const int b = p / 800, rem = p % 800;
    const int4* __restrict__ src = reinterpret_cast<const int4*>(g_actB + (size_t)p * 64);

    int xw[16];
#pragma unroll
    for (int j = 0; j < 4; j++) {
        const int4 v = src[j];
        xw[4 * j + 0] = v.x; xw[4 * j + 1] = v.y; xw[4 * j + 2] = v.z; xw[4 * j + 3] = v.w;
    }
    int acc[36];
#pragma unroll
    for (int o = 0; o < 36; o++) acc[o] = 0;
#pragma unroll
    for (int c4 = 0; c4 < 16; c4++) {
        const int x = xw[c4];
        const int* __restrict__ w = sw_ + c4 * 36;
#pragma unroll
        for (int o = 0; o < 36; o++) acc[o] = __dp4a(x, w[o], acc[o]);
    }
    const float sc = s_sc;
#pragma unroll
    for (int o = 0; o < 36; o++)
        outp[(size_t)(b * 36 + o) * 800 + rem] = (float)acc[o] * sc + __ldg(&b9[o]);
}

// ---------------- launch ----------------
extern "C" void kernel_launch(void* const* d_in, const int* in_sizes, int n_in,
                              void* d_out, int out_size)
{
    const float* x      = (const float*)d_in[0];
    const float* b9     = (const float*)d_in[10];
    const float* scales = (const float*)d_in[19];

    const int wn[9] = {432, 4608, 18432, 36864, 36864, 36864, 36864, 36864, 2304};

    MaxArgs ma;
    for (int i = 0; i < 9; i++) { ma.p[i] = (const float*)d_in[1 + i]; ma.n[i] = wn[i]; }
    k_maxabs<<<9, 256>>>(ma);

    PackArgs pa;
    for (int i = 0; i < 9; i++) pa.w[i] = (const float*)d_in[1 + i];
    k_pack<<<(52560 + 255) / 256, 256>>>(pa);

    BnArgs ba;
    for (int i = 0; i < 8; i++) ba.bn[i] = (const float*)d_in[11 + i];
    ba.scales = scales;
    k_params<<<1, 256>>>(ba);

    cudaFuncSetAttribute(k_conv<16, 64, true,  2>, cudaFuncAttributeMaxDynamicSharedMemorySize, 59472);
    cudaFuncSetAttribute(k_conv<16, 64, false, 2>, cudaFuncAttributeMaxDynamicSharedMemorySize, 59472);

    //                            grid            thr  smem    in out  woff          sRelu sNext blk  H    W
    k_conv_first           <<<dim3(20, 10, 16), 512>>>(x, scales);
    k_conv<4,  32, true, 1><<<dim3(20, 10, 16), 256, 11408>>>(0, 1,   144, scales, 11, 3, 1, 160, 320);
    k_conv<8,  64, true, 2><<<dim3(10,  5, 16), 512, 30672>>>(1, 0,  1296, scales, 12, 4, 2,  80, 160);
    k_conv<16, 64, true, 2><<<dim3( 5,  3, 16), 512, 59472>>>(0, 1,  5904, scales, 13, 5, 3,  40,  80);
    k_conv<16, 64, false,2><<<dim3( 3,  2, 16), 512, 59472>>>(1, 0, 15120, scales, 14, 6, 4,  20,  40);
    k_conv<16, 64, false,2><<<dim3( 3,  2, 16), 512, 59472>>>(0, 1, 24336, scales, 15, 7, 5,  20,  40);
    k_conv<16, 64, false,2><<<dim3( 3,  2, 16), 512, 59472>>>(1, 0, 33552, scales, 16, 8, 6,  20,  40);
    k_conv<16, 64, false,2><<<dim3( 3,  2, 16), 512, 59472>>>(0, 1, 42768, scales, 17, 9, 7,  20,  40);
    k_head<<<50, 256>>>((float*)d_out, b9);
}

// round 11
// speedup vs baseline: 1.3124x; 1.3124x over previous
#include <cuda_runtime.h>

#define EPSB 1e-5f
#define NB 16

// ---------------- device-global scratch (no allocation allowed) ----------------
// activation buffers: packed SIGNED int8 codes, already requantized to the
// CONSUMER block's input scale (producer-side LUT). NHWC.
__device__ __align__(128) unsigned char g_actA[NB * 160 * 320 * 16]; // 13.1 MB
__device__ __align__(128) unsigned char g_actB[NB * 80 * 160 * 32];  //  6.6 MB
__device__ __align__(128) int           g_actC[NB * 320 * 640];      // 13.1 MB (block0 packed input)

// packed int8x4 quantized weights, layout per weight: [tap][cin4][cout]
__device__ int   g_wq[52560];
__device__ float g_sw[9];        // per-tensor weight scales
__device__ float g_A[512];       // per-block (8) x per-channel epilogue scale
__device__ float g_B[512];       // per-block bias
__device__ float g_head_sc;      // s_w9 * scales[9]

// ---------------- prep kernels ----------------
struct MaxArgs { const float* p[9]; int n[9]; };

__global__ void k_maxabs(MaxArgs a) {
    __shared__ float red[8];
    const int b = blockIdx.x;
    const float* __restrict__ w = a.p[b];
    const int n = a.n[b];
    float m = 0.f;
    for (int i = threadIdx.x; i < n; i += blockDim.x) m = fmaxf(m, fabsf(w[i]));
    for (int s = 16; s; s >>= 1) m = fmaxf(m, __shfl_xor_sync(0xffffffffu, m, s));
    if ((threadIdx.x & 31) == 0) red[threadIdx.x >> 5] = m;
    __syncthreads();
    if (threadIdx.x < 32) {
        float v = (threadIdx.x < 8) ? red[threadIdx.x] : 0.f;
        for (int s = 4; s; s >>= 1) v = fmaxf(v, __shfl_xor_sync(0xffffffffu, v, s));
        if (threadIdx.x == 0) g_sw[b] = v / 7.0f;
    }
}

struct PackArgs { const float* w[9]; };

__global__ void k_pack(PackArgs a) {
    const int off[10]  = {0, 144, 1296, 5904, 15120, 24336, 33552, 42768, 51984, 52560};
    const int cinR[9]  = {3, 16, 32, 64, 64, 64, 64, 64, 64};
    const int cin4[9]  = {1, 4, 8, 16, 16, 16, 16, 16, 16};
    const int coutA[9] = {16, 32, 64, 64, 64, 64, 64, 64, 36};
    const int kk[9]    = {3, 3, 3, 3, 3, 3, 3, 3, 1};

    int idx = blockIdx.x * blockDim.x + threadIdx.x;
    if (idx >= 52560) return;
    int wi = 0;
    while (wi < 8 && idx >= off[wi + 1]) wi++;
    const int local = idx - off[wi];
    const int C4 = cin4[wi], CO = coutA[wi], K = kk[wi], CR = cinR[wi];
    const int tap = local / (C4 * CO);
    const int rest = local % (C4 * CO);
    const int c4 = rest / CO, o = rest % CO;
    const int ky = tap / K, kx = tap % K;
    const float s = g_sw[wi];
    const float* __restrict__ w = a.w[wi];
    unsigned packed = 0;
#pragma unroll
    for (int j = 0; j < 4; j++) {
        const int ci = c4 * 4 + j;
        int q = 0;
        if (ci < CR) {
            float v = w[((o * CR + ci) * K + ky) * K + kx];
            q = __float2int_rn(__fdiv_rn(v, s));
            q = min(7, max(-7, q));
        }
        packed |= (unsigned)(q & 255) << (j * 8);
    }
    g_wq[idx] = (int)packed;
}

struct BnArgs { const float* bn[8]; const float* scales; };

__global__ void k_params(BnArgs a) {
    const int couts[8] = {16, 32, 64, 64, 64, 64, 64, 64};
    for (int idx = threadIdx.x; idx < 8 * 64; idx += blockDim.x) {
        const int blk = idx >> 6, c = idx & 63;
        const int C = couts[blk];
        if (c >= C) continue;
        const float* __restrict__ bn = a.bn[blk];
        const float g = bn[c], b = bn[C + c], m = bn[2 * C + c], v = bn[3 * C + c];
        const float inv = __fdiv_rn(g, sqrtf(v + EPSB));
        const float s_in = a.scales[1 + blk];
        const float s_relu = a.scales[10 + blk];
        const float sw = g_sw[blk];
        g_A[idx] = __fdiv_rn(sw * s_in * inv, s_relu);
        g_B[idx] = __fdiv_rn(b - m * inv, s_relu);
    }
    if (threadIdx.x == 0) g_head_sc = g_sw[8] * a.scales[9];
}

// ---------------- input quantize: fp32 NCHW -> packed s1 codes, 1 word/pixel ----------------
// q0 = clamp(rint(x * rcp(s0)), -8, 7); code = lut01[q0+8] (s1 units); 3 codes/word.
__global__ __launch_bounds__(256) void
k_quant0(const float* __restrict__ xin, const float* __restrict__ scales)
{
    __shared__ int lut01[16];
    const int tid = threadIdx.x;
    if (tid < 16) {
        const float s0 = scales[0], s1 = scales[1];
        int v = __float2int_rn(__fdiv_rn((float)(tid - 8) * s0, s1));
        lut01[tid] = min(7, max(-8, v)) & 255;
    }
    __syncthreads();

    const float r0 = __frcp_rn(__ldg(&scales[0]));
    const int p = blockIdx.x * 256 + tid;        // 16*320*640 = 3,276,800 exact
    const int b = p / 204800, rem = p % 204800;
    const size_t base = (size_t)b * 3 * 204800 + rem;
    unsigned pkd = 0;
#pragma unroll
    for (int c = 0; c < 3; c++) {
        const float f = xin[base + (size_t)c * 204800];
        int q0 = __float2int_rn(f * r0);
        q0 = min(7, max(-8, q0));
        pkd |= (unsigned)lut01[q0 + 8] << (8 * c);
    }
    g_actC[p] = (int)pkd;
}

// ---------------- generic fused conv block (quad-per-thread, 4 channel groups) ----------------
// CTA: 256 threads over a 16x16 pre-pool tile. chgrp = tid>>6 selects couts
// [chgrp*CO, ...); quad = tid&63 is a 2x2 pixel block. Weight LDS.128 loads are
// FULL WARP BROADCASTS (all lanes in a warp share chgrp); x window cached in
// regs per c4 -> ~11 dp4a per LDS. Pooling is in-thread (quad owns the 2x2).
// Epilogue: BN -> clamp q15 -> producer-side LUT to next block's input code.
template <int CIN4, int COUT, bool POOL>
__global__ __launch_bounds__(256, 2) void
k_conv(int inSel, int outSel, int woff, const float* __restrict__ scales,
       int sRelu, int sNext, int blk, int H, int W)
{
    constexpr int CO   = COUT / 4;          // couts per thread
    constexpr int CIN  = CIN4 * 4;          // bytes per pixel
    constexpr int XS   = CIN4 | 1;          // odd word stride (bank spread)
    constexpr int NW   = 9 * CIN4 * COUT;

    extern __shared__ int smem[];
    int*   sw_  = smem;                     // weights [tap][c4][o]
    int*   sx   = smem + NW;                // input tile 18x18, packed int8x4
    float* sA   = (float*)(sx + 324 * XS);
    float* sB   = sA + COUT;
    int*   slut = (int*)(sB + COUT);        // q15 -> next-input code (byte)

    const unsigned char* __restrict__ in =
        (inSel == 2) ? (const unsigned char*)g_actC : (inSel ? g_actB : g_actA);
    unsigned char* __restrict__ out = outSel ? g_actB : g_actA;

    const int tid = threadIdx.x;
    if (tid < 16) {
        const float sp = scales[sRelu], sc = scales[sNext];
        int v = __float2int_rn(__fdiv_rn((float)tid * sp, sc));
        slut[tid] = min(7, max(-8, v)) & 255;
    }
    if (tid < COUT) { sA[tid] = g_A[blk * 64 + tid]; sB[tid] = g_B[blk * 64 + tid]; }
    {   // vectorized weight fill (woff, NW are 16B-aligned)
        const int4* __restrict__ wq4 = reinterpret_cast<const int4*>(g_wq + woff);
        int4* sw4 = reinterpret_cast<int4*>(sw_);
        for (int i = tid; i < NW / 4; i += 256) sw4[i] = wq4[i];
    }

    const int b  = blockIdx.z;
    const int x0 = blockIdx.x * 16, y0 = blockIdx.y * 16;

    // cooperative halo tile copy (codes pre-requantized by producer)
    if constexpr (CIN4 >= 4) {
        constexpr int NC16 = CIN4 / 4;
        for (int i = tid; i < 324 * NC16; i += 256) {
            const int pix = i / NC16, c16 = i % NC16;
            const int ty = pix / 18, tx = pix % 18;
            const int iy = y0 + ty - 1, ix = x0 + tx - 1;
            uint4 v = make_uint4(0, 0, 0, 0);
            if (iy >= 0 && iy < H && ix >= 0 && ix < W)
                v = *reinterpret_cast<const uint4*>(
                    in + ((size_t)(b * H + iy) * W + ix) * CIN + c16 * 16);
            int* d = sx + pix * XS + c16 * 4;
            d[0] = (int)v.x; d[1] = (int)v.y; d[2] = (int)v.z; d[3] = (int)v.w;
        }
    } else {
        for (int i = tid; i < 324; i += 256) {
            const int ty = i / 18, tx = i % 18;
            const int iy = y0 + ty - 1, ix = x0 + tx - 1;
            int v = 0;
            if (iy >= 0 && iy < H && ix >= 0 && ix < W)
                v = *reinterpret_cast<const int*>(
                    in + ((size_t)(b * H + iy) * W + ix) * 4);
            sx[i * XS] = v;
        }
    }
    __syncthreads();

    const int chgrp = tid >> 6, q = tid & 63;
    const int chbase = chgrp * CO;
    const int px0 = (q & 7) * 2, py0 = (q >> 3) * 2;

    int acc[4][CO];
#pragma unroll
    for (int p = 0; p < 4; p++)
#pragma unroll
    for (int o = 0; o < CO; o++) acc[p][o] = 0;

    for (int c4 = 0; c4 < CIN4; c4++) {      // rolled: keeps code in I$
        int win[16];                         // 4x4 window, this c4
#pragma unroll
        for (int r = 0; r < 4; r++)
#pragma unroll
        for (int c = 0; c < 4; c++)
            win[r * 4 + c] = sx[((py0 + r) * 18 + px0 + c) * XS + c4];

#pragma unroll
        for (int ky = 0; ky < 3; ky++)
#pragma unroll
        for (int kx = 0; kx < 3; kx++) {
            const int* __restrict__ w = sw_ + ((ky * 3 + kx) * CIN4 + c4) * COUT + chbase;
#pragma unroll
            for (int j = 0; j < CO; j += 4) {
                const int4 w4 = *reinterpret_cast<const int4*>(w + j);   // warp broadcast
#pragma unroll
                for (int p = 0; p < 4; p++) {
                    const int xw = win[((p >> 1) + ky) * 4 + (p & 1) + kx];
                    acc[p][j + 0] = __dp4a(xw, w4.x, acc[p][j + 0]);
                    acc[p][j + 1] = __dp4a(xw, w4.y, acc[p][j + 1]);
                    acc[p][j + 2] = __dp4a(xw, w4.z, acc[p][j + 2]);
                    acc[p][j + 3] = __dp4a(xw, w4.w, acc[p][j + 3]);
                }
            }
        }
    }

    if (POOL) {
        const int gy = y0 + py0, gx = x0 + px0;      // quad base; H,W even
        if (gy < H && gx < W) {
            unsigned pk[CO / 4];
#pragma unroll
            for (int j = 0; j < CO / 4; j++) pk[j] = 0;
#pragma unroll
            for (int o = 0; o < CO; o++) {
                // int-domain pool (A>0 => affine+rint+clip monotone)
                const int m = max(max(acc[0][o], acc[1][o]), max(acc[2][o], acc[3][o]));
                const float y = fmaf((float)m, sA[chbase + o], sB[chbase + o]);
                int qq = __float2int_rn(y);
                qq = min(15, max(0, qq));
                pk[o >> 2] |= (unsigned)slut[qq] << ((o & 3) * 8);
            }
            unsigned char* dst = out
                + ((size_t)(b * (H >> 1) + (gy >> 1)) * (W >> 1) + (gx >> 1)) * COUT + chbase;
            if constexpr (CO == 16)
                *reinterpret_cast<uint4*>(dst) = make_uint4(pk[0], pk[1], pk[2], pk[3]);
            else if constexpr (CO == 8)
                *reinterpret_cast<uint2*>(dst) = make_uint2(pk[0], pk[1]);
            else
                *reinterpret_cast<unsigned*>(dst) = pk[0];
        }
    } else {
#pragma unroll
        for (int p = 0; p < 4; p++) {
            const int gy = y0 + py0 + (p >> 1), gx = x0 + px0 + (p & 1);
            if (gy < H && gx < W) {
                unsigned pk[CO / 4];
#pragma unroll
                for (int j = 0; j < CO / 4; j++) pk[j] = 0;
#pragma unroll
                for (int o = 0; o < CO; o++) {
                    const float y = fmaf((float)acc[p][o], sA[chbase + o], sB[chbase + o]);
                    int qq = __float2int_rn(y);
                    qq = min(15, max(0, qq));
                    pk[o >> 2] |= (unsigned)slut[qq] << ((o & 3) * 8);
                }
                unsigned char* dst = out + ((size_t)(b * H + gy) * W + gx) * COUT + chbase;
                if constexpr (CO == 16)
                    *reinterpret_cast<uint4*>(dst) = make_uint4(pk[0], pk[1], pk[2], pk[3]);
                else if constexpr (CO == 8)
                    *reinterpret_cast<uint2*>(dst) = make_uint2(pk[0], pk[1]);
                else
                    *reinterpret_cast<unsigned*>(dst) = pk[0];
            }
        }
    }
}

// ---------------- head: 1x1 conv (64->36) + bias, fp32 NCHW out ----------------
// Input codes are already in scales[9] units (block7 producer LUT) — no requant.
__global__ __launch_bounds__(256) void
k_head(float* __restrict__ outp, const float* __restrict__ b9)
{
    __shared__ int   sw_[576];
    __shared__ float s_sc;
    const int tid = threadIdx.x;
    if (tid == 0) s_sc = g_head_sc;
    for (int i = tid; i < 576; i += 256) sw_[i] = g_wq[51984 + i];
    __syncthreads();

    const int p = blockIdx.x * 256 + tid;      // 0..12799 = b*800 + y*40 + x
    if (p >= 12800) return;
    const int b = p / 800, rem = p % 800;
    const int4* __restrict__ src = reinterpret_cast<const int4*>(g_actB + (size_t)p * 64);

    int xw[16];
#pragma unroll
    for (int j = 0; j < 4; j++) {
        const int4 v = src[j];
        xw[4 * j + 0] = v.x; xw[4 * j + 1] = v.y; xw[4 * j + 2] = v.z; xw[4 * j + 3] = v.w;
    }
    int acc[36];
#pragma unroll
    for (int o = 0; o < 36; o++) acc[o] = 0;
#pragma unroll
    for (int c4 = 0; c4 < 16; c4++) {
        const int x = xw[c4];
        const int* __restrict__ w = sw_ + c4 * 36;
#pragma unroll
        for (int o = 0; o < 36; o++) acc[o] = __dp4a(x, w[o], acc[o]);
    }
    const float sc = s_sc;
#pragma unroll
    for (int o = 0; o < 36; o++)
        outp[(size_t)(b * 36 + o) * 800 + rem] = (float)acc[o] * sc + __ldg(&b9[o]);
}

// ---------------- launch ----------------
extern "C" void kernel_launch(void* const* d_in, const int* in_sizes, int n_in,
                              void* d_out, int out_size)
{
    const float* x      = (const float*)d_in[0];
    const float* b9     = (const float*)d_in[10];
    const float* scales = (const float*)d_in[19];

    const int wn[9] = {432, 4608, 18432, 36864, 36864, 36864, 36864, 36864, 2304};

    MaxArgs ma;
    for (int i = 0; i < 9; i++) { ma.p[i] = (const float*)d_in[1 + i]; ma.n[i] = wn[i]; }
    k_maxabs<<<9, 256>>>(ma);

    PackArgs pa;
    for (int i = 0; i < 9; i++) pa.w[i] = (const float*)d_in[1 + i];
    k_pack<<<(52560 + 255) / 256, 256>>>(pa);

    BnArgs ba;
    for (int i = 0; i < 8; i++) ba.bn[i] = (const float*)d_in[11 + i];
    ba.scales = scales;
    k_params<<<1, 256>>>(ba);

    cudaFuncSetAttribute(k_conv<16, 64, true >, cudaFuncAttributeMaxDynamicSharedMemorySize, 59472);
    cudaFuncSetAttribute(k_conv<16, 64, false>, cudaFuncAttributeMaxDynamicSharedMemorySize, 59472);

    k_quant0<<<12800, 256>>>(x, scales);

    //                        grid             smem     in out  woff          sRelu sNext blk  H    W
    k_conv<1,  16, true ><<<dim3(40, 20, 16), 256,  2064>>>(2, 0,     0, scales, 10, 2, 0, 320, 640);
    k_conv<4,  32, true ><<<dim3(20, 10, 16), 256, 11408>>>(0, 1,   144, scales, 11, 3, 1, 160, 320);
    k_conv<8,  64, true ><<<dim3(10,  5, 16), 256, 30672>>>(1, 0,  1296, scales, 12, 4, 2,  80, 160);
    k_conv<16, 64, true ><<<dim3( 5,  3, 16), 256, 59472>>>(0, 1,  5904, scales, 13, 5, 3,  40,  80);
    k_conv<16, 64, false><<<dim3( 3,  2, 16), 256, 59472>>>(1, 0, 15120, scales, 14, 6, 4,  20,  40);
    k_conv<16, 64, false><<<dim3( 3,  2, 16), 256, 59472>>>(0, 1, 24336, scales, 15, 7, 5,  20,  40);
    k_conv<16, 64, false><<<dim3( 3,  2, 16), 256, 59472>>>(1, 0, 33552, scales, 16, 8, 6,  20,  40);
    k_conv<16, 64, false><<<dim3( 3,  2, 16), 256, 59472>>>(0, 1, 42768, scales, 17, 9, 7,  20,  40);
    k_head<<<50, 256>>>((float*)d_out, b9);
}

// round 12
// speedup vs baseline: 1.4179x; 1.0804x over previous
#include <cuda_runtime.h>

#define EPSB 1e-5f
#define NB 16

// ---------------- device-global scratch (no allocation allowed) ----------------
// activation buffers: packed SIGNED int8 codes, already requantized to the
// CONSUMER block's input scale (producer-side LUT). NHWC.
__device__ __align__(128) unsigned char g_actA[NB * 160 * 320 * 16]; // 13.1 MB
__device__ __align__(128) unsigned char g_actB[NB * 80 * 160 * 32];  //  6.6 MB

// packed int8x4 quantized weights, layout per weight: [tap][cin4][cout]
__device__ int   g_wq[52560];
__device__ float g_sw[9];        // per-tensor weight scales
__device__ float g_A[512];       // per-block (8) x per-channel epilogue scale
__device__ float g_B[512];       // per-block bias
__device__ float g_head_sc;      // s_w9 * scales[9]

// ---------------- prep kernels ----------------
struct MaxArgs { const float* p[9]; int n[9]; };

__global__ void k_maxabs(MaxArgs a) {
    __shared__ float red[8];
    const int b = blockIdx.x;
    const float* __restrict__ w = a.p[b];
    const int n = a.n[b];
    float m = 0.f;
    for (int i = threadIdx.x; i < n; i += blockDim.x) m = fmaxf(m, fabsf(w[i]));
    for (int s = 16; s; s >>= 1) m = fmaxf(m, __shfl_xor_sync(0xffffffffu, m, s));
    if ((threadIdx.x & 31) == 0) red[threadIdx.x >> 5] = m;
    __syncthreads();
    if (threadIdx.x < 32) {
        float v = (threadIdx.x < 8) ? red[threadIdx.x] : 0.f;
        for (int s = 4; s; s >>= 1) v = fmaxf(v, __shfl_xor_sync(0xffffffffu, v, s));
        if (threadIdx.x == 0) g_sw[b] = v / 7.0f;
    }
}

struct PackArgs { const float* w[9]; };

__global__ void k_pack(PackArgs a) {
    const int off[10]  = {0, 144, 1296, 5904, 15120, 24336, 33552, 42768, 51984, 52560};
    const int cinR[9]  = {3, 16, 32, 64, 64, 64, 64, 64, 64};
    const int cin4[9]  = {1, 4, 8, 16, 16, 16, 16, 16, 16};
    const int coutA[9] = {16, 32, 64, 64, 64, 64, 64, 64, 36};
    const int kk[9]    = {3, 3, 3, 3, 3, 3, 3, 3, 1};

    int idx = blockIdx.x * blockDim.x + threadIdx.x;
    if (idx >= 52560) return;
    int wi = 0;
    while (wi < 8 && idx >= off[wi + 1]) wi++;
    const int local = idx - off[wi];
    const int C4 = cin4[wi], CO = coutA[wi], K = kk[wi], CR = cinR[wi];
    const int tap = local / (C4 * CO);
    const int rest = local % (C4 * CO);
    const int c4 = rest / CO, o = rest % CO;
    const int ky = tap / K, kx = tap % K;
    const float s = g_sw[wi];
    const float* __restrict__ w = a.w[wi];
    unsigned packed = 0;
#pragma unroll
    for (int j = 0; j < 4; j++) {
        const int ci = c4 * 4 + j;
        int q = 0;
        if (ci < CR) {
            float v = w[((o * CR + ci) * K + ky) * K + kx];
            q = __float2int_rn(__fdiv_rn(v, s));
            q = min(7, max(-7, q));
        }
        packed |= (unsigned)(q & 255) << (j * 8);
    }
    g_wq[idx] = (int)packed;
}

struct BnArgs { const float* bn[8]; const float* scales; };

__global__ void k_params(BnArgs a) {
    const int couts[8] = {16, 32, 64, 64, 64, 64, 64, 64};
    for (int idx = threadIdx.x; idx < 8 * 64; idx += blockDim.x) {
        const int blk = idx >> 6, c = idx & 63;
        const int C = couts[blk];
        if (c >= C) continue;
        const float* __restrict__ bn = a.bn[blk];
        const float g = bn[c], b = bn[C + c], m = bn[2 * C + c], v = bn[3 * C + c];
        const float inv = __fdiv_rn(g, sqrtf(v + EPSB));
        const float s_in = a.scales[1 + blk];
        const float s_relu = a.scales[10 + blk];
        const float sw = g_sw[blk];
        g_A[idx] = __fdiv_rn(sw * s_in * inv, s_relu);
        g_B[idx] = __fdiv_rn(b - m * inv, s_relu);
    }
    if (threadIdx.x == 0) g_head_sc = g_sw[8] * a.scales[9];
}

// ---------------- generic fused conv block ----------------
// CHG-way channel split: 256 threads = CHG warp-groups x NQ quads.
//   CHG=4: NQ=64 quads -> 16x16 tile; chgrp = tid>>6 (warp-uniform)
//   CHG=8: NQ=32 quads -> 16x8  tile; chgrp = tid>>5 (warp-uniform)
// Weight LDS.128 loads are FULL WARP BROADCASTS; 4x4 input window cached in
// regs per c4 -> ~11 dp4a per LDS. In-thread 2x2 pooling (quad owns the 2x2).
// FIRST: halo loader reads fp32 NCHW input and quantizes via rcp-mul + lut01
// (identical math to the former k_quant0). Epilogue: BN -> clamp q15 ->
// producer-side LUT to next block's input code.
template <int CIN4, int COUT, bool POOL, int CHG, bool FIRST>
__global__ __launch_bounds__(256, 2) void
k_conv(const float* __restrict__ xin, int inSel, int outSel, int woff,
       const float* __restrict__ scales, int sRelu, int sNext, int blk, int H, int W)
{
    constexpr int NQ   = 256 / CHG;         // quads per channel group
    constexpr int CO   = COUT / CHG;        // couts per thread
    constexpr int TH   = (NQ / 8) * 2;      // tile height (16 or 8); tile width 16
    constexpr int HR   = TH + 2;            // halo rows
    constexpr int CIN  = CIN4 * 4;          // bytes per pixel
    constexpr int XS   = CIN4 | 1;          // odd word stride (bank spread)
    constexpr int NW   = 9 * CIN4 * COUT;

    extern __shared__ int smem[];
    int*   sw_   = smem;                    // weights [tap][c4][o]
    int*   sx    = smem + NW;               // input tile HRx18, packed int8x4
    float* sA    = (float*)(sx + HR * 18 * XS);
    float* sB    = sA + COUT;
    int*   slut  = (int*)(sB + COUT);       // q15 -> next-input code (byte)
    int*   lut01 = slut + 16;               // FIRST only: (q0+8) -> s1 code byte

    const unsigned char* __restrict__ in  = inSel ? g_actB : g_actA;
    unsigned char*       __restrict__ out = outSel ? g_actB : g_actA;

    const int tid = threadIdx.x;
    if (tid < 16) {
        const float sp = scales[sRelu], sc = scales[sNext];
        int v = __float2int_rn(__fdiv_rn((float)tid * sp, sc));
        slut[tid] = min(7, max(-8, v)) & 255;
        if (FIRST) {
            int u = __float2int_rn(__fdiv_rn((float)(tid - 8) * scales[0], scales[1]));
            lut01[tid] = min(7, max(-8, u)) & 255;
        }
    }
    if (tid < COUT) { sA[tid] = g_A[blk * 64 + tid]; sB[tid] = g_B[blk * 64 + tid]; }
    {   // vectorized weight fill (woff, NW are 16B-aligned)
        const int4* __restrict__ wq4 = reinterpret_cast<const int4*>(g_wq + woff);
        int4* sw4 = reinterpret_cast<int4*>(sw_);
        for (int i = tid; i < NW / 4; i += 256) sw4[i] = wq4[i];
    }

    const int b  = blockIdx.z;
    const int x0 = blockIdx.x * 16, y0 = blockIdx.y * TH;

    if constexpr (FIRST) {
        __syncthreads();                    // halo below reads lut01 (smem)
        const float r0 = __frcp_rn(__ldg(&scales[0]));
        for (int i = tid; i < HR * 18; i += 256) {
            const int ty = i / 18, tx = i % 18;
            const int iy = y0 + ty - 1, ix = x0 + tx - 1;
            unsigned pkd = 0;
            if (iy >= 0 && iy < H && ix >= 0 && ix < W) {
                const size_t base = (size_t)b * 3 * H * W + (size_t)iy * W + ix;
#pragma unroll
                for (int c = 0; c < 3; c++) {
                    const float f = xin[base + (size_t)c * H * W];
                    int q0 = __float2int_rn(f * r0);
                    q0 = min(7, max(-8, q0));
                    pkd |= (unsigned)lut01[q0 + 8] << (8 * c);
                }
            }
            sx[i * XS] = (int)pkd;
        }
    } else if constexpr (CIN4 >= 4) {
        constexpr int NC16 = CIN4 / 4;
        for (int i = tid; i < HR * 18 * NC16; i += 256) {
            const int pix = i / NC16, c16 = i % NC16;
            const int ty = pix / 18, tx = pix % 18;
            const int iy = y0 + ty - 1, ix = x0 + tx - 1;
            uint4 v = make_uint4(0, 0, 0, 0);
            if (iy >= 0 && iy < H && ix >= 0 && ix < W)
                v = *reinterpret_cast<const uint4*>(
                    in + ((size_t)(b * H + iy) * W + ix) * CIN + c16 * 16);
            int* d = sx + pix * XS + c16 * 4;
            d[0] = (int)v.x; d[1] = (int)v.y; d[2] = (int)v.z; d[3] = (int)v.w;
        }
    } else {
        for (int i = tid; i < HR * 18; i += 256) {
            const int ty = i / 18, tx = i % 18;
            const int iy = y0 + ty - 1, ix = x0 + tx - 1;
            int v = 0;
            if (iy >= 0 && iy < H && ix >= 0 && ix < W)
                v = *reinterpret_cast<const int*>(
                    in + ((size_t)(b * H + iy) * W + ix) * 4);
            sx[i * XS] = v;
        }
    }
    __syncthreads();

    const int chgrp = tid / NQ, q = tid % NQ;
    const int chbase = chgrp * CO;
    const int px0 = (q & 7) * 2, py0 = (q >> 3) * 2;

    int acc[4][CO];
#pragma unroll
    for (int p = 0; p < 4; p++)
#pragma unroll
    for (int o = 0; o < CO; o++) acc[p][o] = 0;

    for (int c4 = 0; c4 < CIN4; c4++) {      // rolled: keeps code in I$
        int win[16];                         // 4x4 window, this c4
#pragma unroll
        for (int r = 0; r < 4; r++)
#pragma unroll
        for (int c = 0; c < 4; c++)
            win[r * 4 + c] = sx[((py0 + r) * 18 + px0 + c) * XS + c4];

#pragma unroll
        for (int ky = 0; ky < 3; ky++)
#pragma unroll
        for (int kx = 0; kx < 3; kx++) {
            const int* __restrict__ w = sw_ + ((ky * 3 + kx) * CIN4 + c4) * COUT + chbase;
#pragma unroll
            for (int j = 0; j < CO; j += 4) {
                const int4 w4 = *reinterpret_cast<const int4*>(w + j);   // warp broadcast
#pragma unroll
                for (int p = 0; p < 4; p++) {
                    const int xw = win[((p >> 1) + ky) * 4 + (p & 1) + kx];
                    acc[p][j + 0] = __dp4a(xw, w4.x, acc[p][j + 0]);
                    acc[p][j + 1] = __dp4a(xw, w4.y, acc[p][j + 1]);
                    acc[p][j + 2] = __dp4a(xw, w4.z, acc[p][j + 2]);
                    acc[p][j + 3] = __dp4a(xw, w4.w, acc[p][j + 3]);
                }
            }
        }
    }

    if (POOL) {
        const int gy = y0 + py0, gx = x0 + px0;      // quad base; H,W even
        if (gy < H && gx < W) {
            unsigned pk[CO / 4];
#pragma unroll
            for (int j = 0; j < CO / 4; j++) pk[j] = 0;
#pragma unroll
            for (int o = 0; o < CO; o++) {
                // int-domain pool (A>0 => affine+rint+clip monotone)
                const int m = max(max(acc[0][o], acc[1][o]), max(acc[2][o], acc[3][o]));
                const float y = fmaf((float)m, sA[chbase + o], sB[chbase + o]);
                int qq = __float2int_rn(y);
                qq = min(15, max(0, qq));
                pk[o >> 2] |= (unsigned)slut[qq] << ((o & 3) * 8);
            }
            unsigned char* dst = out
                + ((size_t)(b * (H >> 1) + (gy >> 1)) * (W >> 1) + (gx >> 1)) * COUT + chbase;
            if constexpr (CO == 16)
                *reinterpret_cast<uint4*>(dst) = make_uint4(pk[0], pk[1], pk[2], pk[3]);
            else if constexpr (CO == 8)
                *reinterpret_cast<uint2*>(dst) = make_uint2(pk[0], pk[1]);
            else
                *reinterpret_cast<unsigned*>(dst) = pk[0];
        }
    } else {
#pragma unroll
        for (int p = 0; p < 4; p++) {
            const int gy = y0 + py0 + (p >> 1), gx = x0 + px0 + (p & 1);
            if (gy < H && gx < W) {
                unsigned pk[CO / 4];
#pragma unroll
                for (int j = 0; j < CO / 4; j++) pk[j] = 0;
#pragma unroll
                for (int o = 0; o < CO; o++) {
                    const float y = fmaf((float)acc[p][o], sA[chbase + o], sB[chbase + o]);
                    int qq = __float2int_rn(y);
                    qq = min(15, max(0, qq));
                    pk[o >> 2] |= (unsigned)slut[qq] << ((o & 3) * 8);
                }
                unsigned char* dst = out + ((size_t)(b * H + gy) * W + gx) * COUT + chbase;
                if constexpr (CO == 16)
                    *reinterpret_cast<uint4*>(dst) = make_uint4(pk[0], pk[1], pk[2], pk[3]);
                else if constexpr (CO == 8)
                    *reinterpret_cast<uint2*>(dst) = make_uint2(pk[0], pk[1]);
                else
                    *reinterpret_cast<unsigned*>(dst) = pk[0];
            }
        }
    }
}

// ---------------- head: 1x1 conv (64->36) + bias, fp32 NCHW out ----------------
// Input codes are already in scales[9] units (block7 producer LUT) — no requant.
__global__ __launch_bounds__(256) void
k_head(float* __restrict__ outp, const float* __restrict__ b9)
{
    __shared__ int   sw_[576];
    __shared__ float s_sc;
    const int tid = threadIdx.x;
    if (tid == 0) s_sc = g_head_sc;
    for (int i = tid; i < 576; i += 256) sw_[i] = g_wq[51984 + i];
    __syncthreads();

    const int p = blockIdx.x * 256 + tid;      // 0..12799 = b*800 + y*40 + x
    if (p >= 12800) return;
    const int b = p / 800, rem = p % 800;
    const int4* __restrict__ src = reinterpret_cast<const int4*>(g_actB + (size_t)p * 64);

    int xw[16];
#pragma unroll
    for (int j = 0; j < 4; j++) {
        const int4 v = src[j];
        xw[4 * j + 0] = v.x; xw[4 * j + 1] = v.y; xw[4 * j + 2] = v.z; xw[4 * j + 3] = v.w;
    }
    int acc[36];
#pragma unroll
    for (int o = 0; o < 36; o++) acc[o] = 0;
#pragma unroll
    for (int c4 = 0; c4 < 16; c4++) {
        const int x = xw[c4];
        const int* __restrict__ w = sw_ + c4 * 36;
#pragma unroll
        for (int o = 0; o < 36; o++) acc[o] = __dp4a(x, w[o], acc[o]);
    }
    const float sc = s_sc;
#pragma unroll
    for (int o = 0; o < 36; o++)
        outp[(size_t)(b * 36 + o) * 800 + rem] = (float)acc[o] * sc + __ldg(&b9[o]);
}

// ---------------- launch ----------------
extern "C" void kernel_launch(void* const* d_in, const int* in_sizes, int n_in,
                              void* d_out, int out_size)
{
    const float* x      = (const float*)d_in[0];
    const float* b9     = (const float*)d_in[10];
    const float* scales = (const float*)d_in[19];

    const int wn[9] = {432, 4608, 18432, 36864, 36864, 36864, 36864, 36864, 2304};

    MaxArgs ma;
    for (int i = 0; i < 9; i++) { ma.p[i] = (const float*)d_in[1 + i]; ma.n[i] = wn[i]; }
    k_maxabs<<<9, 256>>>(ma);

    PackArgs pa;
    for (int i = 0; i < 9; i++) pa.w[i] = (const float*)d_in[1 + i];
    k_pack<<<(52560 + 255) / 256, 256>>>(pa);

    BnArgs ba;
    for (int i = 0; i < 8; i++) ba.bn[i] = (const float*)d_in[11 + i];
    ba.scales = scales;
    k_params<<<1, 256>>>(ba);

    // >48KB dynamic smem instances (idempotent, capture-safe host calls)
    cudaFuncSetAttribute(k_conv<16, 64, true,  4, false>, cudaFuncAttributeMaxDynamicSharedMemorySize, 59536);
    cudaFuncSetAttribute(k_conv<16, 64, false, 8, false>, cudaFuncAttributeMaxDynamicSharedMemorySize, 49744);

    // smem bytes = 4*(NW + HR*18*XS + 2*COUT + 32)
    //                              grid                smem      in out  woff           sRelu sNext blk  H    W
    k_conv<1,  16, true, 4, true ><<<dim3(40, 20, 16), 256,  2128>>>(x, 0, 0,     0, scales, 10, 2, 0, 320, 640);
    k_conv<4,  32, true, 4, false><<<dim3(20, 10, 16), 256, 11472>>>(x, 0, 1,   144, scales, 11, 3, 1, 160, 320);
    k_conv<8,  64, true, 4, false><<<dim3(10,  5, 16), 256, 30736>>>(x, 1, 0,  1296, scales, 12, 4, 2,  80, 160);
    k_conv<16, 64, true, 4, false><<<dim3( 5,  3, 16), 256, 59536>>>(x, 0, 1,  5904, scales, 13, 5, 3,  40,  80);
    k_conv<16, 64, false,8, false><<<dim3( 3,  3, 16), 256, 49744>>>(x, 1, 0, 15120, scales, 14, 6, 4,  20,  40);
    k_conv<16, 64, false,8, false><<<dim3( 3,  3, 16), 256, 49744>>>(x, 0, 1, 24336, scales, 15, 7, 5,  20,  40);
    k_conv<16, 64, false,8, false><<<dim3( 3,  3, 16), 256, 49744>>>(x, 1, 0, 33552, scales, 16, 8, 6,  20,  40);
    k_conv<16, 64, false,8, false><<<dim3( 3,  3, 16), 256, 49744>>>(x, 0, 1, 42768, scales, 17, 9, 7,  20,  40);
    k_head<<<50, 256>>>((float*)d_out, b9);
}

// round 13
// speedup vs baseline: 1.5646x; 1.1034x over previous
#include <cuda_runtime.h>

#define EPSB 1e-5f
#define NB 16

// ---------------- device-global scratch (no allocation allowed) ----------------
// activation buffers: packed SIGNED int8 codes, already requantized to the
// CONSUMER block's input scale (producer-side LUT). NHWC.
__device__ __align__(128) unsigned char g_actA[NB * 160 * 320 * 16]; // 13.1 MB
__device__ __align__(128) unsigned char g_actB[NB * 80 * 160 * 32];  //  6.6 MB

// packed int8x4 quantized weights, layout per weight: [tap][cin4][cout]
__device__ int   g_wq[52560];
__device__ float g_sw[9];        // per-tensor weight scales
__device__ float g_A[512];       // per-block (8) x per-channel epilogue scale
__device__ float g_B[512];       // per-block bias
__device__ float g_head_sc;      // s_w9 * scales[9]

// ---------------- prep kernels ----------------
struct MaxArgs { const float* p[9]; int n[9]; };

__global__ void k_maxabs(MaxArgs a) {
    __shared__ float red[8];
    const int b = blockIdx.x;
    const float* __restrict__ w = a.p[b];
    const int n = a.n[b];
    float m = 0.f;
    for (int i = threadIdx.x; i < n; i += blockDim.x) m = fmaxf(m, fabsf(w[i]));
    for (int s = 16; s; s >>= 1) m = fmaxf(m, __shfl_xor_sync(0xffffffffu, m, s));
    if ((threadIdx.x & 31) == 0) red[threadIdx.x >> 5] = m;
    __syncthreads();
    if (threadIdx.x < 32) {
        float v = (threadIdx.x < 8) ? red[threadIdx.x] : 0.f;
        for (int s = 4; s; s >>= 1) v = fmaxf(v, __shfl_xor_sync(0xffffffffu, v, s));
        if (threadIdx.x == 0) g_sw[b] = v / 7.0f;
    }
}

struct PackArgs { const float* w[9]; };

__global__ void k_pack(PackArgs a) {
    const int off[10]  = {0, 144, 1296, 5904, 15120, 24336, 33552, 42768, 51984, 52560};
    const int cinR[9]  = {3, 16, 32, 64, 64, 64, 64, 64, 64};
    const int cin4[9]  = {1, 4, 8, 16, 16, 16, 16, 16, 16};
    const int coutA[9] = {16, 32, 64, 64, 64, 64, 64, 64, 36};
    const int kk[9]    = {3, 3, 3, 3, 3, 3, 3, 3, 1};

    int idx = blockIdx.x * blockDim.x + threadIdx.x;
    if (idx >= 52560) return;
    int wi = 0;
    while (wi < 8 && idx >= off[wi + 1]) wi++;
    const int local = idx - off[wi];
    const int C4 = cin4[wi], CO = coutA[wi], K = kk[wi], CR = cinR[wi];
    const int tap = local / (C4 * CO);
    const int rest = local % (C4 * CO);
    const int c4 = rest / CO, o = rest % CO;
    const int ky = tap / K, kx = tap % K;
    const float s = g_sw[wi];
    const float* __restrict__ w = a.w[wi];
    unsigned packed = 0;
#pragma unroll
    for (int j = 0; j < 4; j++) {
        const int ci = c4 * 4 + j;
        int q = 0;
        if (ci < CR) {
            float v = w[((o * CR + ci) * K + ky) * K + kx];
            q = __float2int_rn(__fdiv_rn(v, s));
            q = min(7, max(-7, q));
        }
        packed |= (unsigned)(q & 255) << (j * 8);
    }
    g_wq[idx] = (int)packed;
}

struct BnArgs { const float* bn[8]; const float* scales; };

__global__ void k_params(BnArgs a) {
    const int couts[8] = {16, 32, 64, 64, 64, 64, 64, 64};
    for (int idx = threadIdx.x; idx < 8 * 64; idx += blockDim.x) {
        const int blk = idx >> 6, c = idx & 63;
        const int C = couts[blk];
        if (c >= C) continue;
        const float* __restrict__ bn = a.bn[blk];
        const float g = bn[c], b = bn[C + c], m = bn[2 * C + c], v = bn[3 * C + c];
        const float inv = __fdiv_rn(g, sqrtf(v + EPSB));
        const float s_in = a.scales[1 + blk];
        const float s_relu = a.scales[10 + blk];
        const float sw = g_sw[blk];
        g_A[idx] = __fdiv_rn(sw * s_in * inv, s_relu);
        g_B[idx] = __fdiv_rn(b - m * inv, s_relu);
    }
    if (threadIdx.x == 0) g_head_sc = g_sw[8] * a.scales[9];
}

// ---------------- generic fused conv block ----------------
// CHG-way channel split: 256 threads = CHG warp-groups x NQ quads.
//   CHG=2: NQ=128 quads -> 16x32 tile; CHG=4: NQ=64 -> 16x16; CHG=8: NQ=32 -> 16x8.
// chgrp = tid/NQ is warp-uniform, so weight LDS.128 loads are FULL WARP
// BROADCASTS; 4x4 input window cached in regs per c4 -> ~11 dp4a per LDS.
// In-thread 2x2 pooling (quad owns the 2x2).
// FIRST: halo loader reads fp32 NCHW input and quantizes via rcp-mul + lut01.
// Epilogue: BN -> clamp q15 -> producer-side LUT to next block's input code.
template <int CIN4, int COUT, bool POOL, int CHG, bool FIRST>
__global__ __launch_bounds__(256, 2) void
k_conv(const float* __restrict__ xin, int inSel, int outSel, int woff,
       const float* __restrict__ scales, int sRelu, int sNext, int blk, int H, int W)
{
    constexpr int NQ   = 256 / CHG;         // quads per channel group
    constexpr int CO   = COUT / CHG;        // couts per thread
    constexpr int TH   = (NQ / 8) * 2;      // tile height (32/16/8); tile width 16
    constexpr int HR   = TH + 2;            // halo rows
    constexpr int CIN  = CIN4 * 4;          // bytes per pixel
    constexpr int XS   = CIN4 | 1;          // odd word stride (bank spread)
    constexpr int NW   = 9 * CIN4 * COUT;

    extern __shared__ int smem[];
    int*   sw_   = smem;                    // weights [tap][c4][o]
    int*   sx    = smem + NW;               // input tile HRx18, packed int8x4
    float* sA    = (float*)(sx + HR * 18 * XS);
    float* sB    = sA + COUT;
    int*   slut  = (int*)(sB + COUT);       // q15 -> next-input code (byte)
    int*   lut01 = slut + 16;               // FIRST only: (q0+8) -> s1 code byte

    const unsigned char* __restrict__ in  = inSel ? g_actB : g_actA;
    unsigned char*       __restrict__ out = outSel ? g_actB : g_actA;

    const int tid = threadIdx.x;
    if (tid < 16) {
        const float sp = scales[sRelu], sc = scales[sNext];
        int v = __float2int_rn(__fdiv_rn((float)tid * sp, sc));
        slut[tid] = min(7, max(-8, v)) & 255;
        if (FIRST) {
            int u = __float2int_rn(__fdiv_rn((float)(tid - 8) * scales[0], scales[1]));
            lut01[tid] = min(7, max(-8, u)) & 255;
        }
    }
    if (tid < COUT) { sA[tid] = g_A[blk * 64 + tid]; sB[tid] = g_B[blk * 64 + tid]; }
    {   // vectorized weight fill (woff, NW are 16B-aligned)
        const int4* __restrict__ wq4 = reinterpret_cast<const int4*>(g_wq + woff);
        int4* sw4 = reinterpret_cast<int4*>(sw_);
        for (int i = tid; i < NW / 4; i += 256) sw4[i] = wq4[i];
    }

    const int b  = blockIdx.z;
    const int x0 = blockIdx.x * 16, y0 = blockIdx.y * TH;

    if constexpr (FIRST) {
        __syncthreads();                    // halo below reads lut01 (smem)
        const float r0 = __frcp_rn(__ldg(&scales[0]));
        for (int i = tid; i < HR * 18; i += 256) {
            const int ty = i / 18, tx = i % 18;
            const int iy = y0 + ty - 1, ix = x0 + tx - 1;
            unsigned pkd = 0;
            if (iy >= 0 && iy < H && ix >= 0 && ix < W) {
                const size_t base = (size_t)b * 3 * H * W + (size_t)iy * W + ix;
#pragma unroll
                for (int c = 0; c < 3; c++) {
                    const float f = xin[base + (size_t)c * H * W];
                    int q0 = __float2int_rn(f * r0);
                    q0 = min(7, max(-8, q0));
                    pkd |= (unsigned)lut01[q0 + 8] << (8 * c);
                }
            }
            sx[i * XS] = (int)pkd;
        }
    } else if constexpr (CIN4 >= 4) {
        constexpr int NC16 = CIN4 / 4;
        for (int i = tid; i < HR * 18 * NC16; i += 256) {
            const int pix = i / NC16, c16 = i % NC16;
            const int ty = pix / 18, tx = pix % 18;
            const int iy = y0 + ty - 1, ix = x0 + tx - 1;
            uint4 v = make_uint4(0, 0, 0, 0);
            if (iy >= 0 && iy < H && ix >= 0 && ix < W)
                v = *reinterpret_cast<const uint4*>(
                    in + ((size_t)(b * H + iy) * W + ix) * CIN + c16 * 16);
            int* d = sx + pix * XS + c16 * 4;
            d[0] = (int)v.x; d[1] = (int)v.y; d[2] = (int)v.z; d[3] = (int)v.w;
        }
    } else {
        for (int i = tid; i < HR * 18; i += 256) {
            const int ty = i / 18, tx = i % 18;
            const int iy = y0 + ty - 1, ix = x0 + tx - 1;
            int v = 0;
            if (iy >= 0 && iy < H && ix >= 0 && ix < W)
                v = *reinterpret_cast<const int*>(
                    in + ((size_t)(b * H + iy) * W + ix) * 4);
            sx[i * XS] = v;
        }
    }
    __syncthreads();

    const int chgrp = tid / NQ, q = tid % NQ;
    const int chbase = chgrp * CO;
    const int px0 = (q & 7) * 2, py0 = (q >> 3) * 2;

    int acc[4][CO];
#pragma unroll
    for (int p = 0; p < 4; p++)
#pragma unroll
    for (int o = 0; o < CO; o++) acc[p][o] = 0;

    for (int c4 = 0; c4 < CIN4; c4++) {      // rolled: keeps code in I$
        int win[16];                         // 4x4 window, this c4
#pragma unroll
        for (int r = 0; r < 4; r++)
#pragma unroll
        for (int c = 0; c < 4; c++)
            win[r * 4 + c] = sx[((py0 + r) * 18 + px0 + c) * XS + c4];

#pragma unroll
        for (int ky = 0; ky < 3; ky++)
#pragma unroll
        for (int kx = 0; kx < 3; kx++) {
            const int* __restrict__ w = sw_ + ((ky * 3 + kx) * CIN4 + c4) * COUT + chbase;
#pragma unroll
            for (int j = 0; j < CO; j += 4) {
                const int4 w4 = *reinterpret_cast<const int4*>(w + j);   // warp broadcast
#pragma unroll
                for (int p = 0; p < 4; p++) {
                    const int xw = win[((p >> 1) + ky) * 4 + (p & 1) + kx];
                    acc[p][j + 0] = __dp4a(xw, w4.x, acc[p][j + 0]);
                    acc[p][j + 1] = __dp4a(xw, w4.y, acc[p][j + 1]);
                    acc[p][j + 2] = __dp4a(xw, w4.z, acc[p][j + 2]);
                    acc[p][j + 3] = __dp4a(xw, w4.w, acc[p][j + 3]);
                }
            }
        }
    }

    if (POOL) {
        const int gy = y0 + py0, gx = x0 + px0;      // quad base; H,W even
        if (gy < H && gx < W) {
            unsigned pk[CO / 4];
#pragma unroll
            for (int j = 0; j < CO / 4; j++) pk[j] = 0;
#pragma unroll
            for (int o = 0; o < CO; o++) {
                // int-domain pool (A>0 => affine+rint+clip monotone)
                const int m = max(max(acc[0][o], acc[1][o]), max(acc[2][o], acc[3][o]));
                const float y = fmaf((float)m, sA[chbase + o], sB[chbase + o]);
                int qq = __float2int_rn(y);
                qq = min(15, max(0, qq));
                pk[o >> 2] |= (unsigned)slut[qq] << ((o & 3) * 8);
            }
            unsigned char* dst = out
                + ((size_t)(b * (H >> 1) + (gy >> 1)) * (W >> 1) + (gx >> 1)) * COUT + chbase;
            if constexpr (CO == 16)
                *reinterpret_cast<uint4*>(dst) = make_uint4(pk[0], pk[1], pk[2], pk[3]);
            else if constexpr (CO == 8)
                *reinterpret_cast<uint2*>(dst) = make_uint2(pk[0], pk[1]);
            else
                *reinterpret_cast<unsigned*>(dst) = pk[0];
        }
    } else {
#pragma unroll
        for (int p = 0; p < 4; p++) {
            const int gy = y0 + py0 + (p >> 1), gx = x0 + px0 + (p & 1);
            if (gy < H && gx < W) {
                unsigned pk[CO / 4];
#pragma unroll
                for (int j = 0; j < CO / 4; j++) pk[j] = 0;
#pragma unroll
                for (int o = 0; o < CO; o++) {
                    const float y = fmaf((float)acc[p][o], sA[chbase + o], sB[chbase + o]);
                    int qq = __float2int_rn(y);
                    qq = min(15, max(0, qq));
                    pk[o >> 2] |= (unsigned)slut[qq] << ((o & 3) * 8);
                }
                unsigned char* dst = out + ((size_t)(b * H + gy) * W + gx) * COUT + chbase;
                if constexpr (CO == 16)
                    *reinterpret_cast<uint4*>(dst) = make_uint4(pk[0], pk[1], pk[2], pk[3]);
                else if constexpr (CO == 8)
                    *reinterpret_cast<uint2*>(dst) = make_uint2(pk[0], pk[1]);
                else
                    *reinterpret_cast<unsigned*>(dst) = pk[0];
            }
        }
    }
}

// ---------------- head: 1x1 conv (64->36) + bias, fp32 NCHW out ----------------
// Input codes are already in scales[9] units (block7 producer LUT) — no requant.
__global__ __launch_bounds__(256) void
k_head(float* __restrict__ outp, const float* __restrict__ b9)
{
    __shared__ int   sw_[576];
    __shared__ float s_sc;
    const int tid = threadIdx.x;
    if (tid == 0) s_sc = g_head_sc;
    for (int i = tid; i < 576; i += 256) sw_[i] = g_wq[51984 + i];
    __syncthreads();

    const int p = blockIdx.x * 256 + tid;      // 0..12799 = b*800 + y*40 + x
    if (p >= 12800) return;
    const int b = p / 800, rem = p % 800;
    const int4* __restrict__ src = reinterpret_cast<const int4*>(g_actB + (size_t)p * 64);

    int xw[16];
#pragma unroll
    for (int j = 0; j < 4; j++) {
        const int4 v = src[j];
        xw[4 * j + 0] = v.x; xw[4 * j + 1] = v.y; xw[4 * j + 2] = v.z; xw[4 * j + 3] = v.w;
    }
    int acc[36];
#pragma unroll
    for (int o = 0; o < 36; o++) acc[o] = 0;
#pragma unroll
    for (int c4 = 0; c4 < 16; c4++) {
        const int x = xw[c4];
        const int* __restrict__ w = sw_ + c4 * 36;
#pragma unroll
        for (int o = 0; o < 36; o++) acc[o] = __dp4a(x, w[o], acc[o]);
    }
    const float sc = s_sc;
#pragma unroll
    for (int o = 0; o < 36; o++)
        outp[(size_t)(b * 36 + o) * 800 + rem] = (float)acc[o] * sc + __ldg(&b9[o]);
}

// ---------------- launch ----------------
extern "C" void kernel_launch(void* const* d_in, const int* in_sizes, int n_in,
                              void* d_out, int out_size)
{
    const float* x      = (const float*)d_in[0];
    const float* b9     = (const float*)d_in[10];
    const float* scales = (const float*)d_in[19];

    const int wn[9] = {432, 4608, 18432, 36864, 36864, 36864, 36864, 36864, 2304};

    MaxArgs ma;
    for (int i = 0; i < 9; i++) { ma.p[i] = (const float*)d_in[1 + i]; ma.n[i] = wn[i]; }
    k_maxabs<<<9, 256>>>(ma);

    PackArgs pa;
    for (int i = 0; i < 9; i++) pa.w[i] = (const float*)d_in[1 + i];
    k_pack<<<(52560 + 255) / 256, 256>>>(pa);

    BnArgs ba;
    for (int i = 0; i < 8; i++) ba.bn[i] = (const float*)d_in[11 + i];
    ba.scales = scales;
    k_params<<<1, 256>>>(ba);

    // >48KB dynamic smem instances (idempotent, capture-safe host calls)
    cudaFuncSetAttribute(k_conv<16, 64, true,  4, false>, cudaFuncAttributeMaxDynamicSharedMemorySize, 59536);
    cudaFuncSetAttribute(k_conv<16, 64, true,  8, false>, cudaFuncAttributeMaxDynamicSharedMemorySize, 49744);
    cudaFuncSetAttribute(k_conv<16, 64, false, 8, false>, cudaFuncAttributeMaxDynamicSharedMemorySize, 49744);

    // smem bytes = 4*(NW + HR*18*XS + 2*COUT + 32)
    //                              grid                smem      in out  woff           sRelu sNext blk  H    W
    k_conv<1,  16, true, 2, true ><<<dim3(40, 10, 16), 256,  3280>>>(x, 0, 0,     0, scales, 10, 2, 0, 320, 640);
    k_conv<4,  32, true, 4, false><<<dim3(20, 10, 16), 256, 11472>>>(x, 0, 1,   144, scales, 11, 3, 1, 160, 320);
    k_conv<8,  64, true, 4, false><<<dim3(10,  5, 16), 256, 30736>>>(x, 1, 0,  1296, scales, 12, 4, 2,  80, 160);
    k_conv<16, 64, true, 8, false><<<dim3( 5,  5, 16), 256, 49744>>>(x, 0, 1,  5904, scales, 13, 5, 3,  40,  80);
    k_conv<16, 64, false,8, false><<<dim3( 3,  3, 16), 256, 49744>>>(x, 1, 0, 15120, scales, 14, 6, 4,  20,  40);
    k_conv<16, 64, false,8, false><<<dim3( 3,  3, 16), 256, 49744>>>(x, 0, 1, 24336, scales, 15, 7, 5,  20,  40);
    k_conv<16, 64, false,8, false><<<dim3( 3,  3, 16), 256, 49744>>>(x, 1, 0, 33552, scales, 16, 8, 6,  20,  40);
    k_conv<16, 64, false,8, false><<<dim3( 3,  3, 16), 256, 49744>>>(x, 0, 1, 42768, scales, 17, 9, 7,  20,  40);
    k_head<<<50, 256>>>((float*)d_out, b9);
}

// round 14
// speedup vs baseline: 1.6160x; 1.0328x over previous
#include <cuda_runtime.h>

#define EPSB 1e-5f
#define NB 16

// ---------------- device-global scratch (no allocation allowed) ----------------
// activation buffers: packed SIGNED int8 codes, already requantized to the
// CONSUMER block's input scale (producer-side LUT). NHWC.
__device__ __align__(128) unsigned char g_actA[NB * 160 * 320 * 16]; // 13.1 MB
__device__ __align__(128) unsigned char g_actB[NB * 80 * 160 * 32];  //  6.6 MB

// packed int8x4 quantized weights, layout per weight: [tap][cin4][cout]
__device__ int   g_wq[52560];
__device__ float g_sw[9];        // per-tensor weight scales
__device__ float g_A[512];       // per-block (8) x per-channel epilogue scale
__device__ float g_B[512];       // per-block bias
__device__ float g_head_sc;      // s_w9 * scales[9]

// ---------------- prep kernels ----------------
struct MaxArgs { const float* p[9]; int n[9]; };

__global__ void k_maxabs(MaxArgs a) {
    __shared__ float red[8];
    const int b = blockIdx.x;
    const float* __restrict__ w = a.p[b];
    const int n = a.n[b];
    float m = 0.f;
    for (int i = threadIdx.x; i < n; i += blockDim.x) m = fmaxf(m, fabsf(w[i]));
    for (int s = 16; s; s >>= 1) m = fmaxf(m, __shfl_xor_sync(0xffffffffu, m, s));
    if ((threadIdx.x & 31) == 0) red[threadIdx.x >> 5] = m;
    __syncthreads();
    if (threadIdx.x < 32) {
        float v = (threadIdx.x < 8) ? red[threadIdx.x] : 0.f;
        for (int s = 4; s; s >>= 1) v = fmaxf(v, __shfl_xor_sync(0xffffffffu, v, s));
        if (threadIdx.x == 0) g_sw[b] = v / 7.0f;
    }
}

struct PackArgs { const float* w[9]; };

__global__ void k_pack(PackArgs a) {
    const int off[10]  = {0, 144, 1296, 5904, 15120, 24336, 33552, 42768, 51984, 52560};
    const int cinR[9]  = {3, 16, 32, 64, 64, 64, 64, 64, 64};
    const int cin4[9]  = {1, 4, 8, 16, 16, 16, 16, 16, 16};
    const int coutA[9] = {16, 32, 64, 64, 64, 64, 64, 64, 36};
    const int kk[9]    = {3, 3, 3, 3, 3, 3, 3, 3, 1};

    int idx = blockIdx.x * blockDim.x + threadIdx.x;
    if (idx >= 52560) return;
    int wi = 0;
    while (wi < 8 && idx >= off[wi + 1]) wi++;
    const int local = idx - off[wi];
    const int C4 = cin4[wi], CO = coutA[wi], K = kk[wi], CR = cinR[wi];
    const int tap = local / (C4 * CO);
    const int rest = local % (C4 * CO);
    const int c4 = rest / CO, o = rest % CO;
    const int ky = tap / K, kx = tap % K;
    const float s = g_sw[wi];
    const float* __restrict__ w = a.w[wi];
    unsigned packed = 0;
#pragma unroll
    for (int j = 0; j < 4; j++) {
        const int ci = c4 * 4 + j;
        int q = 0;
        if (ci < CR) {
            float v = w[((o * CR + ci) * K + ky) * K + kx];
            q = __float2int_rn(__fdiv_rn(v, s));
            q = min(7, max(-7, q));
        }
        packed |= (unsigned)(q & 255) << (j * 8);
    }
    g_wq[idx] = (int)packed;
}

struct BnArgs { const float* bn[8]; const float* scales; };

__global__ void k_params(BnArgs a) {
    const int couts[8] = {16, 32, 64, 64, 64, 64, 64, 64};
    for (int idx = threadIdx.x; idx < 8 * 64; idx += blockDim.x) {
        const int blk = idx >> 6, c = idx & 63;
        const int C = couts[blk];
        if (c >= C) continue;
        const float* __restrict__ bn = a.bn[blk];
        const float g = bn[c], b = bn[C + c], m = bn[2 * C + c], v = bn[3 * C + c];
        const float inv = __fdiv_rn(g, sqrtf(v + EPSB));
        const float s_in = a.scales[1 + blk];
        const float s_relu = a.scales[10 + blk];
        const float sw = g_sw[blk];
        g_A[idx] = __fdiv_rn(sw * s_in * inv, s_relu);
        g_B[idx] = __fdiv_rn(b - m * inv, s_relu);
    }
    if (threadIdx.x == 0) g_head_sc = g_sw[8] * a.scales[9];
}

// ---------------- generic fused conv block ----------------
// CHG-way channel split: 256 threads = CHG groups x NQ quads.
//   CHG=2: 16x32 tile; CHG=4: 16x16; CHG=8: 16x8; CHG=16: 16x4.
// chgrp is warp-uniform for CHG<=8 (weight LDS.128 = full warp broadcast);
// CHG=16 gives 2 addresses/warp (2-way, acceptable for the occupancy gain on
// tiny late layers). 4x4 input window cached in regs per c4.
// In-thread 2x2 pooling (quad owns the 2x2).
// MINB: __launch_bounds__ min-blocks (4 => ptxas caps regs at 64 -> 4 CTAs/SM).
// FIRST: halo loader reads fp32 NCHW input and quantizes via rcp-mul + lut01.
// Epilogue: BN -> clamp q15 -> producer-side LUT to next block's input code.
template <int CIN4, int COUT, bool POOL, int CHG, bool FIRST, int MINB>
__global__ __launch_bounds__(256, MINB) void
k_conv(const float* __restrict__ xin, int inSel, int outSel, int woff,
       const float* __restrict__ scales, int sRelu, int sNext, int blk, int H, int W)
{
    constexpr int NQ   = 256 / CHG;         // quads per channel group
    constexpr int CO   = COUT / CHG;        // couts per thread
    constexpr int TH   = (NQ / 8) * 2;      // tile height (32/16/8/4); tile width 16
    constexpr int HR   = TH + 2;            // halo rows
    constexpr int CIN  = CIN4 * 4;          // bytes per pixel
    constexpr int XS   = CIN4 | 1;          // odd word stride (bank spread)
    constexpr int NW   = 9 * CIN4 * COUT;

    extern __shared__ int smem[];
    int*   sw_   = smem;                    // weights [tap][c4][o]
    int*   sx    = smem + NW;               // input tile HRx18, packed int8x4
    float* sA    = (float*)(sx + HR * 18 * XS);
    float* sB    = sA + COUT;
    int*   slut  = (int*)(sB + COUT);       // q15 -> next-input code (byte)
    int*   lut01 = slut + 16;               // FIRST only: (q0+8) -> s1 code byte

    const unsigned char* __restrict__ in  = inSel ? g_actB : g_actA;
    unsigned char*       __restrict__ out = outSel ? g_actB : g_actA;

    const int tid = threadIdx.x;
    if (tid < 16) {
        const float sp = scales[sRelu], sc = scales[sNext];
        int v = __float2int_rn(__fdiv_rn((float)tid * sp, sc));
        slut[tid] = min(7, max(-8, v)) & 255;
        if (FIRST) {
            int u = __float2int_rn(__fdiv_rn((float)(tid - 8) * scales[0], scales[1]));
            lut01[tid] = min(7, max(-8, u)) & 255;
        }
    }
    if (tid < COUT) { sA[tid] = g_A[blk * 64 + tid]; sB[tid] = g_B[blk * 64 + tid]; }
    {   // vectorized weight fill (woff, NW are 16B-aligned)
        const int4* __restrict__ wq4 = reinterpret_cast<const int4*>(g_wq + woff);
        int4* sw4 = reinterpret_cast<int4*>(sw_);
        for (int i = tid; i < NW / 4; i += 256) sw4[i] = wq4[i];
    }

    const int b  = blockIdx.z;
    const int x0 = blockIdx.x * 16, y0 = blockIdx.y * TH;

    if constexpr (FIRST) {
        __syncthreads();                    // halo below reads lut01 (smem)
        const float r0 = __frcp_rn(__ldg(&scales[0]));
        for (int i = tid; i < HR * 18; i += 256) {
            const int ty = i / 18, tx = i % 18;
            const int iy = y0 + ty - 1, ix = x0 + tx - 1;
            unsigned pkd = 0;
            if (iy >= 0 && iy < H && ix >= 0 && ix < W) {
                const size_t base = (size_t)b * 3 * H * W + (size_t)iy * W + ix;
#pragma unroll
                for (int c = 0; c < 3; c++) {
                    const float f = xin[base + (size_t)c * H * W];
                    int q0 = __float2int_rn(f * r0);
                    q0 = min(7, max(-8, q0));
                    pkd |= (unsigned)lut01[q0 + 8] << (8 * c);
                }
            }
            sx[i * XS] = (int)pkd;
        }
    } else if constexpr (CIN4 >= 4) {
        constexpr int NC16 = CIN4 / 4;
        for (int i = tid; i < HR * 18 * NC16; i += 256) {
            const int pix = i / NC16, c16 = i % NC16;
            const int ty = pix / 18, tx = pix % 18;
            const int iy = y0 + ty - 1, ix = x0 + tx - 1;
            uint4 v = make_uint4(0, 0, 0, 0);
            if (iy >= 0 && iy < H && ix >= 0 && ix < W)
                v = *reinterpret_cast<const uint4*>(
                    in + ((size_t)(b * H + iy) * W + ix) * CIN + c16 * 16);
            int* d = sx + pix * XS + c16 * 4;
            d[0] = (int)v.x; d[1] = (int)v.y; d[2] = (int)v.z; d[3] = (int)v.w;
        }
    } else {
        for (int i = tid; i < HR * 18; i += 256) {
            const int ty = i / 18, tx = i % 18;
            const int iy = y0 + ty - 1, ix = x0 + tx - 1;
            int v = 0;
            if (iy >= 0 && iy < H && ix >= 0 && ix < W)
                v = *reinterpret_cast<const int*>(
                    in + ((size_t)(b * H + iy) * W + ix) * 4);
            sx[i * XS] = v;
        }
    }
    __syncthreads();

    const int chgrp = tid / NQ, q = tid % NQ;
    const int chbase = chgrp * CO;
    const int px0 = (q & 7) * 2, py0 = (q >> 3) * 2;

    int acc[4][CO];
#pragma unroll
    for (int p = 0; p < 4; p++)
#pragma unroll
    for (int o = 0; o < CO; o++) acc[p][o] = 0;

    for (int c4 = 0; c4 < CIN4; c4++) {      // rolled: keeps code in I$
        int win[16];                         // 4x4 window, this c4
#pragma unroll
        for (int r = 0; r < 4; r++)
#pragma unroll
        for (int c = 0; c < 4; c++)
            win[r * 4 + c] = sx[((py0 + r) * 18 + px0 + c) * XS + c4];

#pragma unroll
        for (int ky = 0; ky < 3; ky++)
#pragma unroll
        for (int kx = 0; kx < 3; kx++) {
            const int* __restrict__ w = sw_ + ((ky * 3 + kx) * CIN4 + c4) * COUT + chbase;
#pragma unroll
            for (int j = 0; j < CO; j += 4) {
                const int4 w4 = *reinterpret_cast<const int4*>(w + j);   // warp broadcast
#pragma unroll
                for (int p = 0; p < 4; p++) {
                    const int xw = win[((p >> 1) + ky) * 4 + (p & 1) + kx];
                    acc[p][j + 0] = __dp4a(xw, w4.x, acc[p][j + 0]);
                    acc[p][j + 1] = __dp4a(xw, w4.y, acc[p][j + 1]);
                    acc[p][j + 2] = __dp4a(xw, w4.z, acc[p][j + 2]);
                    acc[p][j + 3] = __dp4a(xw, w4.w, acc[p][j + 3]);
                }
            }
        }
    }

    if (POOL) {
        const int gy = y0 + py0, gx = x0 + px0;      // quad base; H,W even
        if (gy < H && gx < W) {
            unsigned pk[CO / 4];
#pragma unroll
            for (int j = 0; j < CO / 4; j++) pk[j] = 0;
#pragma unroll
            for (int o = 0; o < CO; o++) {
                // int-domain pool (A>0 => affine+rint+clip monotone)
                const int m = max(max(acc[0][o], acc[1][o]), max(acc[2][o], acc[3][o]));
                const float y = fmaf((float)m, sA[chbase + o], sB[chbase + o]);
                int qq = __float2int_rn(y);
                qq = min(15, max(0, qq));
                pk[o >> 2] |= (unsigned)slut[qq] << ((o & 3) * 8);
            }
            unsigned char* dst = out
                + ((size_t)(b * (H >> 1) + (gy >> 1)) * (W >> 1) + (gx >> 1)) * COUT + chbase;
            if constexpr (CO == 16)
                *reinterpret_cast<uint4*>(dst) = make_uint4(pk[0], pk[1], pk[2], pk[3]);
            else if constexpr (CO == 8)
                *reinterpret_cast<uint2*>(dst) = make_uint2(pk[0], pk[1]);
            else
                *reinterpret_cast<unsigned*>(dst) = pk[0];
        }
    } else {
#pragma unroll
        for (int p = 0; p < 4; p++) {
            const int gy = y0 + py0 + (p >> 1), gx = x0 + px0 + (p & 1);
            if (gy < H && gx < W) {
                unsigned pk[CO / 4];
#pragma unroll
                for (int j = 0; j < CO / 4; j++) pk[j] = 0;
#pragma unroll
                for (int o = 0; o < CO; o++) {
                    const float y = fmaf((float)acc[p][o], sA[chbase + o], sB[chbase + o]);
                    int qq = __float2int_rn(y);
                    qq = min(15, max(0, qq));
                    pk[o >> 2] |= (unsigned)slut[qq] << ((o & 3) * 8);
                }
                unsigned char* dst = out + ((size_t)(b * H + gy) * W + gx) * COUT + chbase;
                if constexpr (CO == 16)
                    *reinterpret_cast<uint4*>(dst) = make_uint4(pk[0], pk[1], pk[2], pk[3]);
                else if constexpr (CO == 8)
                    *reinterpret_cast<uint2*>(dst) = make_uint2(pk[0], pk[1]);
                else
                    *reinterpret_cast<unsigned*>(dst) = pk[0];
            }
        }
    }
}

// ---------------- head: 1x1 conv (64->36) + bias, fp32 NCHW out ----------------
// Input codes are already in scales[9] units (block7 producer LUT) — no requant.
__global__ __launch_bounds__(256) void
k_head(float* __restrict__ outp, const float* __restrict__ b9)
{
    __shared__ int   sw_[576];
    __shared__ float s_sc;
    const int tid = threadIdx.x;
    if (tid == 0) s_sc = g_head_sc;
    for (int i = tid; i < 576; i += 256) sw_[i] = g_wq[51984 + i];
    __syncthreads();

    const int p = blockIdx.x * 256 + tid;      // 0..12799 = b*800 + y*40 + x
    if (p >= 12800) return;
    const int b = p / 800, rem = p % 800;
    const int4* __restrict__ src = reinterpret_cast<const int4*>(g_actB + (size_t)p * 64);

    int xw[16];
#pragma unroll
    for (int j = 0; j < 4; j++) {
        const int4 v = src[j];
        xw[4 * j + 0] = v.x; xw[4 * j + 1] = v.y; xw[4 * j + 2] = v.z; xw[4 * j + 3] = v.w;
    }
    int acc[36];
#pragma unroll
    for (int o = 0; o < 36; o++) acc[o] = 0;
#pragma unroll
    for (int c4 = 0; c4 < 16; c4++) {
        const int x = xw[c4];
        const int* __restrict__ w = sw_ + c4 * 36;
#pragma unroll
        for (int o = 0; o < 36; o++) acc[o] = __dp4a(x, w[o], acc[o]);
    }
    const float sc = s_sc;
#pragma unroll
    for (int o = 0; o < 36; o++)
        outp[(size_t)(b * 36 + o) * 800 + rem] = (float)acc[o] * sc + __ldg(&b9[o]);
}

// ---------------- launch ----------------
extern "C" void kernel_launch(void* const* d_in, const int* in_sizes, int n_in,
                              void* d_out, int out_size)
{
    const float* x      = (const float*)d_in[0];
    const float* b9     = (const float*)d_in[10];
    const float* scales = (const float*)d_in[19];

    const int wn[9] = {432, 4608, 18432, 36864, 36864, 36864, 36864, 36864, 2304};

    MaxArgs ma;
    for (int i = 0; i < 9; i++) { ma.p[i] = (const float*)d_in[1 + i]; ma.n[i] = wn[i]; }
    k_maxabs<<<9, 256>>>(ma);

    PackArgs pa;
    for (int i = 0; i < 9; i++) pa.w[i] = (const float*)d_in[1 + i];
    k_pack<<<(52560 + 255) / 256, 256>>>(pa);

    BnArgs ba;
    for (int i = 0; i < 8; i++) ba.bn[i] = (const float*)d_in[11 + i];
    ba.scales = scales;
    k_params<<<1, 256>>>(ba);

    // smem bytes = 4*(NW + HR*18*XS + 2*COUT + 32); all instances < 48KB now.
    //                                   grid                smem      in out  woff           sRelu sNext blk  H    W
    k_conv<1,  16, true,  2, true, 4><<<dim3(40, 10, 16), 256,  3280>>>(x, 0, 0,     0, scales, 10, 2, 0, 320, 640);
    k_conv<4,  32, true,  4, false,4><<<dim3(20, 10, 16), 256, 11472>>>(x, 0, 1,   144, scales, 11, 3, 1, 160, 320);
    k_conv<8,  64, true,  8, false,4><<<dim3(10, 10, 16), 256, 25552>>>(x, 1, 0,  1296, scales, 12, 4, 2,  80, 160);
    k_conv<16, 64, true, 16, false,4><<<dim3( 5, 10, 16), 256, 44848>>>(x, 0, 1,  5904, scales, 13, 5, 3,  40,  80);
    k_conv<16, 64, false,16, false,4><<<dim3( 3,  5, 16), 256, 44848>>>(x, 1, 0, 15120, scales, 14, 6, 4,  20,  40);
    k_conv<16, 64, false,16, false,4><<<dim3( 3,  5, 16), 256, 44848>>>(x, 0, 1, 24336, scales, 15, 7, 5,  20,  40);
    k_conv<16, 64, false,16, false,4><<<dim3( 3,  5, 16), 256, 44848>>>(x, 1, 0, 33552, scales, 16, 8, 6,  20,  40);
    k_conv<16, 64, false,16, false,4><<<dim3( 3,  5, 16), 256, 44848>>>(x, 0, 1, 42768, scales, 17, 9, 7,  20,  40);
    k_head<<<50, 256>>>((float*)d_out, b9);
}